// round 1
// baseline (speedup 1.0000x reference)
#include <cuda_runtime.h>
#include <math.h>
#include <stdint.h>

// Problem constants
#define N_IMG     16
#define N_CH      3
#define NSLICE    (N_IMG * N_CH)          // 48
#define BINS      64
#define SLICE_ELEMS (1024 * 1024)

// Histogram kernel config
#define HTHREADS  256
#define BPS       9                        // blocks per slice -> 432 blocks total
#define HSMEM_BYTES (2 * BINS * HTHREADS * 2)   // 2 replicas x 64 bins x 256 tid x uint16 = 64 KB

// Params layout (in_ch,out_ch row-major), per reference
#define P_W1 0
#define P_B1 24576
#define P_W2 24704
#define P_B2 28800
#define P_G  28832

// Global per-(image,channel) histogram, fp32 counts
__device__ float g_hist[NSLICE * BINS];

__global__ void zero_hist_kernel() {
    int i = blockIdx.x * blockDim.x + threadIdx.x;
    if (i < NSLICE * BINS) g_hist[i] = 0.0f;
}

__global__ __launch_bounds__(HTHREADS, 3)
void hist_kernel(const float* __restrict__ img) {
    extern __shared__ unsigned short sh16[];   // [2][BINS][HTHREADS]
    const int tid = threadIdx.x;

    // zero private histograms (as uint32 for speed: 32768 halves = 16384 words)
    unsigned int* shz = reinterpret_cast<unsigned int*>(sh16);
    #pragma unroll
    for (int i = tid; i < 2 * BINS * HTHREADS / 2; i += HTHREADS) shz[i] = 0u;
    __syncthreads();

    const int slice = blockIdx.x / BPS;
    const int chunk = blockIdx.x % BPS;
    const float4* base = reinterpret_cast<const float4*>(img + (size_t)slice * SLICE_ELEMS);
    const int n4   = SLICE_ELEMS / 4;                 // 262144
    const int per  = (n4 + BPS - 1) / BPS;            // 29128
    const int start = chunk * per;
    const int end   = min(start + per, n4);

    // replica 0 for .x/.z, replica 1 for .y/.w -> two independent RMW chains
    unsigned short* h0 = sh16 + tid;                   // [bin*HTHREADS + tid]
    unsigned short* h1 = sh16 + BINS * HTHREADS + tid;

    for (int i = start + tid; i < end; i += HTHREADS) {
        float4 v = base[i];
        int b0 = (int)(v.x * 64.0f); b0 = b0 < 0 ? 0 : (b0 > 63 ? 63 : b0);
        int b1 = (int)(v.y * 64.0f); b1 = b1 < 0 ? 0 : (b1 > 63 ? 63 : b1);
        int b2 = (int)(v.z * 64.0f); b2 = b2 < 0 ? 0 : (b2 > 63 ? 63 : b2);
        int b3 = (int)(v.w * 64.0f); b3 = b3 < 0 ? 0 : (b3 > 63 ? 63 : b3);
        h0[b0 * HTHREADS] += 1;
        h1[b1 * HTHREADS] += 1;
        h0[b2 * HTHREADS] += 1;
        h1[b3 * HTHREADS] += 1;
    }
    __syncthreads();

    // Tree-reduce along the tid dimension using paired-uint16 adds.
    // View as [128][128] uint32 (128 logical bins b' = r*64+b, 128 tid-pairs).
    unsigned int* sh32 = reinterpret_cast<unsigned int*>(sh16);
    #pragma unroll
    for (int s = 64; s >= 1; s >>= 1) {
        for (int idx = tid; idx < 128 * s; idx += HTHREADS) {
            int b = idx / s;
            int i = idx - b * s;
            sh32[b * 128 + i] += sh32[b * 128 + i + s];
        }
        __syncthreads();
    }

    if (tid < BINS) {
        unsigned int a = sh32[tid * 128];
        unsigned int c = sh32[(tid + BINS) * 128];
        float tot = (float)((a & 0xFFFFu) + (a >> 16) + (c & 0xFFFFu) + (c >> 16));
        atomicAdd(&g_hist[slice * BINS + tid], tot);
    }
}

// One block, 512 threads: hist[16,192] @ W1[192,128] +b1, relu, @ W2[128,32] +b2+g, sigmoid
#define MLP_THREADS 512
#define MLP_SMEM_FLOATS (24576 + 4096 + 3072 + 2048)
#define MLP_SMEM_BYTES  (MLP_SMEM_FLOATS * 4)

__global__ __launch_bounds__(MLP_THREADS, 1)
void mlp_kernel(const float* __restrict__ params, float* __restrict__ out) {
    extern __shared__ float smem[];
    float* s_w1   = smem;                 // 24576
    float* s_w2   = s_w1 + 24576;         // 4096
    float* s_hist = s_w2 + 4096;          // 3072  (== [16][192])
    float* s_h1   = s_hist + 3072;        // 2048  (== [16][128])

    const int tid = threadIdx.x;

    // stage weights (float4 coalesced) and histogram
    #pragma unroll
    for (int i = tid; i < 24576 / 4; i += MLP_THREADS)
        reinterpret_cast<float4*>(s_w1)[i] = reinterpret_cast<const float4*>(params + P_W1)[i];
    #pragma unroll
    for (int i = tid; i < 4096 / 4; i += MLP_THREADS)
        reinterpret_cast<float4*>(s_w2)[i] = reinterpret_cast<const float4*>(params + P_W2)[i];
    #pragma unroll
    for (int i = tid; i < 3072; i += MLP_THREADS)
        s_hist[i] = g_hist[i];
    __syncthreads();

    // Layer 1: h1[n][j], j = tid&127, n in {ng*4 .. ng*4+3}, ng = tid>>7
    {
        const int j  = tid & 127;
        const int ng = tid >> 7;
        float acc0, acc1, acc2, acc3;
        acc0 = acc1 = acc2 = acc3 = params[P_B1 + j];
        const float* h = s_hist + (ng * 4) * 192;
        #pragma unroll 8
        for (int c = 0; c < 192; c++) {
            float w = s_w1[c * 128 + j];
            acc0 = fmaf(h[c],           w, acc0);
            acc1 = fmaf(h[192 + c],     w, acc1);
            acc2 = fmaf(h[384 + c],     w, acc2);
            acc3 = fmaf(h[576 + c],     w, acc3);
        }
        s_h1[(ng * 4 + 0) * 128 + j] = fmaxf(acc0, 0.0f);
        s_h1[(ng * 4 + 1) * 128 + j] = fmaxf(acc1, 0.0f);
        s_h1[(ng * 4 + 2) * 128 + j] = fmaxf(acc2, 0.0f);
        s_h1[(ng * 4 + 3) * 128 + j] = fmaxf(acc3, 0.0f);
    }
    __syncthreads();

    // Layer 2 + sigmoid: out[n][k], n = tid>>5, k = tid&31
    {
        const int n = tid >> 5;
        const int k = tid & 31;
        float a = params[P_B2 + k] + params[P_G];
        const float* h = s_h1 + n * 128;
        #pragma unroll 8
        for (int c = 0; c < 128; c++)
            a = fmaf(h[c], s_w2[c * 32 + k], a);
        out[n * 32 + k] = 1.0f / (1.0f + expf(-a));
    }
}

extern "C" void kernel_launch(void* const* d_in, const int* in_sizes, int n_in,
                              void* d_out, int out_size) {
    const float* img    = (const float*)d_in[0];
    const float* params = (const float*)d_in[1];
    float* out          = (float*)d_out;

    static bool attr_set = false;
    if (!attr_set) {
        cudaFuncSetAttribute(hist_kernel, cudaFuncAttributeMaxDynamicSharedMemorySize, HSMEM_BYTES);
        cudaFuncSetAttribute(mlp_kernel,  cudaFuncAttributeMaxDynamicSharedMemorySize, MLP_SMEM_BYTES);
        attr_set = true;
    }

    zero_hist_kernel<<<(NSLICE * BINS + 255) / 256, 256>>>();
    hist_kernel<<<NSLICE * BPS, HTHREADS, HSMEM_BYTES>>>(img);
    mlp_kernel<<<1, MLP_THREADS, MLP_SMEM_BYTES>>>(params, out);
}

// round 2
// speedup vs baseline: 1.0239x; 1.0239x over previous
#include <cuda_runtime.h>
#include <math.h>
#include <stdint.h>

// Problem constants
#define N_IMG     16
#define N_CH      3
#define NSLICE    (N_IMG * N_CH)          // 48
#define BINS      64
#define SLICE_ELEMS (1024 * 1024)

// Histogram kernel config
#define HTHREADS  256
#define BPS       9                               // blocks per slice -> 432 blocks
#define NBLOCKS   (NSLICE * BPS)
#define HSMEM_BYTES (BINS * HTHREADS * 4)         // [64][256] uint32 = 64 KB

// Params layout (in_ch,out_ch row-major), per reference
#define P_W1 0
#define P_B1 24576
#define P_W2 24704
#define P_B2 28800
#define P_G  28832

// Per-block partial histograms (plain stores, fully overwritten each call)
__device__ float g_part[NBLOCKS * BINS];

__global__ __launch_bounds__(HTHREADS, 3)
void hist_kernel(const float* __restrict__ img) {
    extern __shared__ unsigned int hh[];   // [BINS][HTHREADS] packed: lo=+1 counts, hi=+65536 counts
    const int tid = threadIdx.x;

    #pragma unroll
    for (int i = tid; i < BINS * HTHREADS; i += HTHREADS) hh[i] = 0u;
    __syncthreads();

    const int slice = blockIdx.x / BPS;
    const int chunk = blockIdx.x % BPS;
    const float4* base = reinterpret_cast<const float4*>(img + (size_t)slice * SLICE_ELEMS);
    const int n4   = SLICE_ELEMS / 4;                 // 262144
    const int per  = (n4 + BPS - 1) / BPS;            // 29128
    const int start = chunk * per;
    const int end   = min(start + per, n4);

    unsigned int* h = hh + tid;   // word index bin*256 + tid -> bank = tid%32, conflict-free

#define INC1(v)  { int b = (int)((v) * 64.0f); b = min(b, 63); h[b * HTHREADS] += 1u; }
#define INC64K(v){ int b = (int)((v) * 64.0f); b = min(b, 63); h[b * HTHREADS] += 65536u; }

    int i = start + tid;
    for (; i + HTHREADS < end; i += 2 * HTHREADS) {
        float4 a = base[i];
        float4 c = base[i + HTHREADS];
        INC1(a.x); INC64K(a.y); INC1(a.z); INC64K(a.w);
        INC1(c.x); INC64K(c.y); INC1(c.z); INC64K(c.w);
    }
    if (i < end) {
        float4 a = base[i];
        INC1(a.x); INC64K(a.y); INC1(a.z); INC64K(a.w);
    }
#undef INC1
#undef INC64K
    __syncthreads();

    // Tree-reduce along tid. Halves stay < 65536 even adversarially (<=58256/half).
    #pragma unroll
    for (int s = HTHREADS / 2; s >= 1; s >>= 1) {
        for (int idx = tid; idx < BINS * s; idx += HTHREADS) {
            int b = idx / s;
            int j = idx - b * s;
            hh[b * HTHREADS + j] += hh[b * HTHREADS + j + s];
        }
        __syncthreads();
    }

    if (tid < BINS) {
        unsigned int a = hh[tid * HTHREADS];
        g_part[blockIdx.x * BINS + tid] = (float)((a & 0xFFFFu) + (a >> 16));
    }
}

// One block, 512 threads: reduce partials -> hist[16,192] @ W1[192,128] +b1, relu,
// @ W2[128,32] +b2+g, sigmoid
#define MLP_THREADS 512
#define MLP_SMEM_FLOATS (24576 + 4096 + 3072 + 2048)
#define MLP_SMEM_BYTES  (MLP_SMEM_FLOATS * 4)

__global__ __launch_bounds__(MLP_THREADS, 1)
void mlp_kernel(const float* __restrict__ params, float* __restrict__ out) {
    extern __shared__ float smem[];
    float* s_w1   = smem;                 // 24576
    float* s_w2   = s_w1 + 24576;         // 4096
    float* s_hist = s_w2 + 4096;          // 3072  (== [16][192])
    float* s_h1   = s_hist + 3072;        // 2048  (== [16][128])

    const int tid = threadIdx.x;

    #pragma unroll
    for (int i = tid; i < 24576 / 4; i += MLP_THREADS)
        reinterpret_cast<float4*>(s_w1)[i] = reinterpret_cast<const float4*>(params + P_W1)[i];
    #pragma unroll
    for (int i = tid; i < 4096 / 4; i += MLP_THREADS)
        reinterpret_cast<float4*>(s_w2)[i] = reinterpret_cast<const float4*>(params + P_W2)[i];

    // Reduce per-block partials: s_hist[n][c*64+b] = sum_chunk g_part[((n*3+c)*BPS+chunk)*64+b]
    #pragma unroll
    for (int i = tid; i < 3072; i += MLP_THREADS) {
        int n   = i / 192;
        int col = i - n * 192;
        int c   = col >> 6;
        int b   = col & 63;
        const float* p = g_part + ((n * 3 + c) * BPS) * BINS + b;
        float s = 0.0f;
        #pragma unroll
        for (int k = 0; k < BPS; k++) s += p[k * BINS];
        s_hist[i] = s;
    }
    __syncthreads();

    // Layer 1: h1[n][j], j = tid&127, n in {ng*4 .. ng*4+3}, ng = tid>>7
    {
        const int j  = tid & 127;
        const int ng = tid >> 7;
        float acc0, acc1, acc2, acc3;
        acc0 = acc1 = acc2 = acc3 = params[P_B1 + j];
        const float* hrow = s_hist + (ng * 4) * 192;
        #pragma unroll 8
        for (int c = 0; c < 192; c++) {
            float w = s_w1[c * 128 + j];
            acc0 = fmaf(hrow[c],       w, acc0);
            acc1 = fmaf(hrow[192 + c], w, acc1);
            acc2 = fmaf(hrow[384 + c], w, acc2);
            acc3 = fmaf(hrow[576 + c], w, acc3);
        }
        s_h1[(ng * 4 + 0) * 128 + j] = fmaxf(acc0, 0.0f);
        s_h1[(ng * 4 + 1) * 128 + j] = fmaxf(acc1, 0.0f);
        s_h1[(ng * 4 + 2) * 128 + j] = fmaxf(acc2, 0.0f);
        s_h1[(ng * 4 + 3) * 128 + j] = fmaxf(acc3, 0.0f);
    }
    __syncthreads();

    // Layer 2 + sigmoid: out[n][k], n = tid>>5, k = tid&31
    {
        const int n = tid >> 5;
        const int k = tid & 31;
        float a = params[P_B2 + k] + params[P_G];
        const float* hrow = s_h1 + n * 128;
        #pragma unroll 8
        for (int c = 0; c < 128; c++)
            a = fmaf(hrow[c], s_w2[c * 32 + k], a);
        out[n * 32 + k] = 1.0f / (1.0f + expf(-a));
    }
}

extern "C" void kernel_launch(void* const* d_in, const int* in_sizes, int n_in,
                              void* d_out, int out_size) {
    const float* img    = (const float*)d_in[0];
    const float* params = (const float*)d_in[1];
    float* out          = (float*)d_out;

    static bool attr_set = false;
    if (!attr_set) {
        cudaFuncSetAttribute(hist_kernel, cudaFuncAttributeMaxDynamicSharedMemorySize, HSMEM_BYTES);
        cudaFuncSetAttribute(mlp_kernel,  cudaFuncAttributeMaxDynamicSharedMemorySize, MLP_SMEM_BYTES);
        attr_set = true;
    }

    hist_kernel<<<NBLOCKS, HTHREADS, HSMEM_BYTES>>>(img);
    mlp_kernel<<<1, MLP_THREADS, MLP_SMEM_BYTES>>>(params, out);
}

// round 3
// speedup vs baseline: 1.1094x; 1.0834x over previous
#include <cuda_runtime.h>
#include <math.h>
#include <stdint.h>

// Problem constants
#define N_IMG     16
#define N_CH      3
#define NSLICE    (N_IMG * N_CH)          // 48
#define BINS      64
#define SLICE_ELEMS (1024 * 1024)

// Histogram kernel config
#define HTHREADS  256
#define BPS       9                               // blocks per slice -> 432 blocks
#define NBLOCKS   (NSLICE * BPS)
#define HSMEM_BYTES (BINS * HTHREADS * 4)         // [64][256] uint32 = 64 KB

// Params layout (in_ch,out_ch row-major), per reference
#define P_W1 0
#define P_B1 24576
#define P_W2 24704
#define P_B2 28800
#define P_G  28832

// Per-block partial histograms (plain stores, fully overwritten each call)
__device__ float g_part[NBLOCKS * BINS];

__global__ __launch_bounds__(HTHREADS, 3)
void hist_kernel(const float* __restrict__ img) {
    extern __shared__ unsigned int hh[];   // [BINS][HTHREADS]: lo half counts +1, hi half +65536
    const int tid = threadIdx.x;

    #pragma unroll
    for (int i = tid; i < BINS * HTHREADS; i += HTHREADS) hh[i] = 0u;
    __syncthreads();

    const int slice = blockIdx.x / BPS;
    const int chunk = blockIdx.x % BPS;
    const float4* base = reinterpret_cast<const float4*>(img + (size_t)slice * SLICE_ELEMS);
    const int n4   = SLICE_ELEMS / 4;                 // 262144
    const int per  = (n4 + BPS - 1) / BPS;            // 29128
    const int start = chunk * per;
    const int end   = min(start + per, n4);

    unsigned int* h = hh + tid;   // word index bin*256 + tid -> bank = tid%32, conflict-free

#define PROC(v4) { \
        int b0 = min((int)((v4).x * 64.0f), 63); \
        int b1 = min((int)((v4).y * 64.0f), 63); \
        int b2 = min((int)((v4).z * 64.0f), 63); \
        int b3 = min((int)((v4).w * 64.0f), 63); \
        h[b0 * HTHREADS] += 1u; \
        h[b1 * HTHREADS] += 65536u; \
        h[b2 * HTHREADS] += 1u; \
        h[b3 * HTHREADS] += 65536u; }

    int i = start + tid;
    // Unroll 4: batch 4 independent LDG.128 up front for DRAM latency hiding
    for (; i + 3 * HTHREADS < end; i += 4 * HTHREADS) {
        float4 a = base[i];
        float4 b = base[i + HTHREADS];
        float4 c = base[i + 2 * HTHREADS];
        float4 d = base[i + 3 * HTHREADS];
        PROC(a); PROC(b); PROC(c); PROC(d);
    }
    for (; i < end; i += HTHREADS) {
        float4 a = base[i];
        PROC(a);
    }
#undef PROC
    __syncthreads();

    // Tree-reduce along tid. Halves stay < 65536 even adversarially.
    #pragma unroll
    for (int s = HTHREADS / 2; s >= 1; s >>= 1) {
        for (int idx = tid; idx < BINS * s; idx += HTHREADS) {
            int b = idx / s;
            int j = idx - b * s;
            hh[b * HTHREADS + j] += hh[b * HTHREADS + j + s];
        }
        __syncthreads();
    }

    if (tid < BINS) {
        unsigned int a = hh[tid * HTHREADS];
        g_part[blockIdx.x * BINS + tid] = (float)((a & 0xFFFFu) + (a >> 16));
    }
}

// MLP: grid=4, block=512. Each 128-thread group g handles image n = blockIdx.x*4+g.
// Block stages W1 (96 KB) + W2 (16 KB) once, shared by 4 groups.
#define MLP_BLOCKS  4
#define MLP_THREADS 512
// floats: W1 24576 + W2 4096 + hist 4*192 + h1 4*128 + l2 4*128
#define MLP_SMEM_FLOATS (24576 + 4096 + 768 + 512 + 512)
#define MLP_SMEM_BYTES  (MLP_SMEM_FLOATS * 4)

__global__ __launch_bounds__(MLP_THREADS, 1)
void mlp_kernel(const float* __restrict__ params, float* __restrict__ out) {
    extern __shared__ float smem[];
    float* s_w1   = smem;                 // [192][128]
    float* s_w2   = s_w1 + 24576;         // [128][32]
    float* s_hist = s_w2 + 4096;          // [4][192]
    float* s_h1   = s_hist + 768;         // [4][128]
    float* s_l2   = s_h1 + 512;           // [4][128] layer-2 partials

    const int tid = threadIdx.x;
    const int g   = tid >> 7;             // group 0..3
    const int lt  = tid & 127;            // lane within group
    const int n   = blockIdx.x * 4 + g;   // image index

    // Stage weights (float4 coalesced)
    #pragma unroll
    for (int i = tid; i < 24576 / 4; i += MLP_THREADS)
        reinterpret_cast<float4*>(s_w1)[i] = reinterpret_cast<const float4*>(params + P_W1)[i];
    #pragma unroll
    for (int i = tid; i < 4096 / 4; i += MLP_THREADS)
        reinterpret_cast<float4*>(s_w2)[i] = reinterpret_cast<const float4*>(params + P_W2)[i];

    // Reduce per-block partials into this block's 4 hist rows.
    // s_hist[g][c*64+b] = sum_k g_part[(( (bid*4+g)*3 + c)*BPS + k)*64 + b]
    #pragma unroll
    for (int i = tid; i < 4 * 192; i += MLP_THREADS) {
        int gg  = i / 192;
        int col = i - gg * 192;
        int c   = col >> 6;
        int b   = col & 63;
        const float* p = g_part + (((blockIdx.x * 4 + gg) * 3 + c) * BPS) * BINS + b;
        float s = 0.0f;
        #pragma unroll
        for (int k = 0; k < BPS; k++) s += p[k * BINS];
        s_hist[i] = s;
    }
    __syncthreads();

    // Layer 1: thread lt computes h1[n][lt]
    {
        const float* hrow = s_hist + g * 192;
        float acc = params[P_B1 + lt];
        #pragma unroll 16
        for (int c = 0; c < 192; c++)
            acc = fmaf(hrow[c], s_w1[c * 128 + lt], acc);
        s_h1[g * 128 + lt] = fmaxf(acc, 0.0f);
    }
    __syncthreads();

    // Layer 2: quarter q = lt>>5 sums c in [q*32, q*32+32) for output k = lt&31
    {
        const int q = lt >> 5;
        const int k = lt & 31;
        const float* hrow = s_h1 + g * 128 + q * 32;
        float a = 0.0f;
        #pragma unroll
        for (int c = 0; c < 32; c++)
            a = fmaf(hrow[c], s_w2[(q * 32 + c) * 32 + k], a);
        s_l2[g * 128 + q * 32 + k] = a;
    }
    __syncthreads();

    if (lt < 32) {
        const int k = lt;
        float a = params[P_B2 + k] + params[P_G]
                + s_l2[g * 128 + k] + s_l2[g * 128 + 32 + k]
                + s_l2[g * 128 + 64 + k] + s_l2[g * 128 + 96 + k];
        out[n * 32 + k] = 1.0f / (1.0f + expf(-a));
    }
}

extern "C" void kernel_launch(void* const* d_in, const int* in_sizes, int n_in,
                              void* d_out, int out_size) {
    const float* img    = (const float*)d_in[0];
    const float* params = (const float*)d_in[1];
    float* out          = (float*)d_out;

    static bool attr_set = false;
    if (!attr_set) {
        cudaFuncSetAttribute(hist_kernel, cudaFuncAttributeMaxDynamicSharedMemorySize, HSMEM_BYTES);
        cudaFuncSetAttribute(mlp_kernel,  cudaFuncAttributeMaxDynamicSharedMemorySize, MLP_SMEM_BYTES);
        attr_set = true;
    }

    hist_kernel<<<NBLOCKS, HTHREADS, HSMEM_BYTES>>>(img);
    mlp_kernel<<<MLP_BLOCKS, MLP_THREADS, MLP_SMEM_BYTES>>>(params, out);
}

// round 4
// speedup vs baseline: 1.1369x; 1.0248x over previous
#include <cuda_runtime.h>
#include <math.h>
#include <stdint.h>

// Problem constants
#define N_IMG     16
#define N_CH      3
#define NSLICE    (N_IMG * N_CH)          // 48
#define BINS      64
#define SLICE_ELEMS (1024 * 1024)

// Histogram kernel config
#define HTHREADS  256
#define BPS       9                               // blocks per slice -> 432 blocks
#define NBLOCKS   (NSLICE * BPS)
#define HSMEM_BYTES (BINS * HTHREADS * 4)         // [64][256] uint32 = 64 KB

// Params layout (in_ch,out_ch row-major), per reference
#define P_W1 0
#define P_B1 24576
#define P_W2 24704
#define P_B2 28800
#define P_G  28832

// Per-block partial histograms (plain stores, fully overwritten each call)
__device__ float g_part[NBLOCKS * BINS];

__global__ __launch_bounds__(HTHREADS, 3)
void hist_kernel(const float* __restrict__ img) {
    extern __shared__ unsigned int hh[];   // [BINS][HTHREADS]: lo half counts +1, hi half +65536
    const int tid = threadIdx.x;

    #pragma unroll
    for (int i = tid; i < BINS * HTHREADS; i += HTHREADS) hh[i] = 0u;
    __syncthreads();

    const int slice = blockIdx.x / BPS;
    const int chunk = blockIdx.x % BPS;
    const float4* base = reinterpret_cast<const float4*>(img + (size_t)slice * SLICE_ELEMS);
    const int n4   = SLICE_ELEMS / 4;                 // 262144
    const int per  = (n4 + BPS - 1) / BPS;            // 29128
    const int start = chunk * per;
    const int end   = min(start + per, n4);

    unsigned int* h = hh + tid;   // word index bin*256 + tid -> bank = tid%32, conflict-free

#define PROC(v4) { \
        int b0 = min((int)((v4).x * 64.0f), 63); \
        int b1 = min((int)((v4).y * 64.0f), 63); \
        int b2 = min((int)((v4).z * 64.0f), 63); \
        int b3 = min((int)((v4).w * 64.0f), 63); \
        h[b0 * HTHREADS] += 1u; \
        h[b1 * HTHREADS] += 65536u; \
        h[b2 * HTHREADS] += 1u; \
        h[b3 * HTHREADS] += 65536u; }

    int i = start + tid;
    for (; i + 3 * HTHREADS < end; i += 4 * HTHREADS) {
        float4 a = __ldcs(base + i);
        float4 b = __ldcs(base + i + HTHREADS);
        float4 c = __ldcs(base + i + 2 * HTHREADS);
        float4 d = __ldcs(base + i + 3 * HTHREADS);
        PROC(a); PROC(b); PROC(c); PROC(d);
    }
    for (; i < end; i += HTHREADS) {
        float4 a = __ldcs(base + i);
        PROC(a);
    }
#undef PROC
    __syncthreads();

    // Tree-reduce along tid. Halves stay < 65536 even adversarially.
    #pragma unroll
    for (int s = HTHREADS / 2; s >= 1; s >>= 1) {
        for (int idx = tid; idx < BINS * s; idx += HTHREADS) {
            int b = idx / s;
            int j = idx - b * s;
            hh[b * HTHREADS + j] += hh[b * HTHREADS + j + s];
        }
        __syncthreads();
    }

    if (tid < BINS) {
        unsigned int a = hh[tid * HTHREADS];
        g_part[blockIdx.x * BINS + tid] = (float)((a & 0xFFFFu) + (a >> 16));
    }
}

// MLP with PDL: grid=16 (one image per block), 256 threads.
// Pre-sync: stage all weights (overlaps with hist via programmatic launch).
// Post-sync: reduce g_part for this image + 2 tiny GEMV layers.
#define MLP_BLOCKS  16
#define MLP_THREADS 256
// floats: W1 24576 + W2 4096 + hist 192 + l1 partials 256 + h1 128 + l2 partials 128
#define MLP_SMEM_FLOATS (24576 + 4096 + 192 + 256 + 128 + 128)
#define MLP_SMEM_BYTES  (MLP_SMEM_FLOATS * 4)

__global__ __launch_bounds__(MLP_THREADS, 1)
void mlp_kernel(const float* __restrict__ params, float* __restrict__ out) {
    extern __shared__ float smem[];
    float* s_w1   = smem;                 // [192][128]
    float* s_w2   = s_w1 + 24576;         // [128][32]
    float* s_hist = s_w2 + 4096;          // [192]
    float* s_p1   = s_hist + 192;         // [2][128] layer-1 partials
    float* s_h1   = s_p1 + 256;           // [128]
    float* s_l2   = s_h1 + 128;           // [4][32] layer-2 partials

    const int tid = threadIdx.x;
    const int n   = blockIdx.x;

    // ---- Pre-sync: stage weights (independent of hist results) ----
    #pragma unroll
    for (int i = tid; i < 24576 / 4; i += MLP_THREADS)
        reinterpret_cast<float4*>(s_w1)[i] = reinterpret_cast<const float4*>(params + P_W1)[i];
    #pragma unroll
    for (int i = tid; i < 4096 / 4; i += MLP_THREADS)
        reinterpret_cast<float4*>(s_w2)[i] = reinterpret_cast<const float4*>(params + P_W2)[i];

    // ---- Wait for hist_kernel's g_part writes ----
    cudaGridDependencySynchronize();

    // Reduce per-chunk partials for this image: s_hist[c*64+b]
    if (tid < 192) {
        int c = tid >> 6;
        int b = tid & 63;
        const float* p = g_part + ((n * 3 + c) * BPS) * BINS + b;
        float s = 0.0f;
        #pragma unroll
        for (int k = 0; k < BPS; k++) s += p[k * BINS];
        s_hist[tid] = s;
    }
    __syncthreads();

    // Layer 1: j = tid&127, half = tid>>7 covers c in [half*96, half*96+96)
    {
        const int j    = tid & 127;
        const int half = tid >> 7;
        const int c0   = half * 96;
        float acc = 0.0f;
        #pragma unroll 16
        for (int c = c0; c < c0 + 96; c++)
            acc = fmaf(s_hist[c], s_w1[c * 128 + j], acc);
        s_p1[half * 128 + j] = acc;
    }
    __syncthreads();
    if (tid < 128)
        s_h1[tid] = fmaxf(s_p1[tid] + s_p1[128 + tid] + params[P_B1 + tid], 0.0f);
    __syncthreads();

    // Layer 2: threads 0..127: quarter q = tid>>5 covers c in [q*32, q*32+32), k = tid&31
    if (tid < 128) {
        const int q = tid >> 5;
        const int k = tid & 31;
        float a = 0.0f;
        #pragma unroll
        for (int c = q * 32; c < q * 32 + 32; c++)
            a = fmaf(s_h1[c], s_w2[c * 32 + k], a);
        s_l2[tid] = a;
    }
    __syncthreads();

    if (tid < 32) {
        float a = params[P_B2 + tid] + params[P_G]
                + s_l2[tid] + s_l2[32 + tid] + s_l2[64 + tid] + s_l2[96 + tid];
        out[n * 32 + tid] = 1.0f / (1.0f + expf(-a));
    }
}

extern "C" void kernel_launch(void* const* d_in, const int* in_sizes, int n_in,
                              void* d_out, int out_size) {
    const float* img    = (const float*)d_in[0];
    const float* params = (const float*)d_in[1];
    float* out          = (float*)d_out;

    static bool attr_set = false;
    if (!attr_set) {
        cudaFuncSetAttribute(hist_kernel, cudaFuncAttributeMaxDynamicSharedMemorySize, HSMEM_BYTES);
        cudaFuncSetAttribute(mlp_kernel,  cudaFuncAttributeMaxDynamicSharedMemorySize, MLP_SMEM_BYTES);
        attr_set = true;
    }

    hist_kernel<<<NBLOCKS, HTHREADS, HSMEM_BYTES>>>(img);

    // PDL launch: mlp starts during hist, stages weights, then grid-dep-syncs.
    cudaLaunchConfig_t cfg = {};
    cfg.gridDim  = dim3(MLP_BLOCKS, 1, 1);
    cfg.blockDim = dim3(MLP_THREADS, 1, 1);
    cfg.dynamicSmemBytes = MLP_SMEM_BYTES;
    cudaLaunchAttribute attrs[1];
    attrs[0].id = cudaLaunchAttributeProgrammaticStreamSerialization;
    attrs[0].val.programmaticStreamSerializationAllowed = 1;
    cfg.attrs = attrs;
    cfg.numAttrs = 1;
    cudaLaunchKernelEx(&cfg, mlp_kernel, params, out);
}

// round 5
// speedup vs baseline: 1.2126x; 1.0665x over previous
#include <cuda_runtime.h>
#include <math.h>
#include <stdint.h>

// Problem constants
#define N_IMG     16
#define N_CH      3
#define NSLICE    (N_IMG * N_CH)          // 48
#define BINS      64
#define SLICE_ELEMS (1024 * 1024)

// Histogram kernel config
#define HTHREADS  256
#define BPS       9                               // blocks per slice -> 432 blocks
#define NBLOCKS   (NSLICE * BPS)
#define HSMEM_BYTES (BINS * HTHREADS * 4)         // [64][256] uint32 = 64 KB

// Params layout (in_ch,out_ch row-major), per reference
#define P_W1 0
#define P_B1 24576
#define P_W2 24704
#define P_B2 28800
#define P_G  28832

// Per-block partial histograms (plain stores, fully overwritten each call)
__device__ float g_part[NBLOCKS * BINS];

// Empty kernels: shift ncu's (-s 5 -c 1) capture onto hist_kernel (4 launches/call,
// 5 mod 4 = 1 -> second launch = hist).
__global__ void pad_kernel() {}

__global__ __launch_bounds__(HTHREADS, 3)
void hist_kernel(const float* __restrict__ img) {
    extern __shared__ unsigned int hh[];   // [BINS][HTHREADS]: lo half counts +1, hi half +65536
    const int tid = threadIdx.x;

    #pragma unroll
    for (int i = tid; i < BINS * HTHREADS; i += HTHREADS) hh[i] = 0u;
    __syncthreads();

    const int slice = blockIdx.x / BPS;
    const int chunk = blockIdx.x % BPS;
    const float4* base = reinterpret_cast<const float4*>(img + (size_t)slice * SLICE_ELEMS);
    const int n4   = SLICE_ELEMS / 4;                 // 262144
    const int per  = (n4 + BPS - 1) / BPS;            // 29128
    const int start = chunk * per;
    const int end   = min(start + per, n4);

    unsigned int* h = hh + tid;   // word index bin*256 + tid -> bank = tid%32, conflict-free

#define PROC(v4) { \
        int b0 = min((int)((v4).x * 64.0f), 63); \
        int b1 = min((int)((v4).y * 64.0f), 63); \
        int b2 = min((int)((v4).z * 64.0f), 63); \
        int b3 = min((int)((v4).w * 64.0f), 63); \
        h[b0 * HTHREADS] += 1u; \
        h[b1 * HTHREADS] += 65536u; \
        h[b2 * HTHREADS] += 1u; \
        h[b3 * HTHREADS] += 65536u; }

    int i = start + tid;
    // Unroll 8: batch 8 independent LDG.128 up front (98 KB in flight per SM)
    for (; i + 7 * HTHREADS < end; i += 8 * HTHREADS) {
        float4 v0 = __ldcs(base + i);
        float4 v1 = __ldcs(base + i + 1 * HTHREADS);
        float4 v2 = __ldcs(base + i + 2 * HTHREADS);
        float4 v3 = __ldcs(base + i + 3 * HTHREADS);
        float4 v4 = __ldcs(base + i + 4 * HTHREADS);
        float4 v5 = __ldcs(base + i + 5 * HTHREADS);
        float4 v6 = __ldcs(base + i + 6 * HTHREADS);
        float4 v7 = __ldcs(base + i + 7 * HTHREADS);
        PROC(v0); PROC(v1); PROC(v2); PROC(v3);
        PROC(v4); PROC(v5); PROC(v6); PROC(v7);
    }
    for (; i < end; i += HTHREADS) {
        float4 a = __ldcs(base + i);
        PROC(a);
    }
#undef PROC
    __syncthreads();

    // Warp-shuffle epilogue: warp w reduces bins 8w..8w+7.
    // Packed block-total per bin <= 58256 + 58256*2^16 < 2^32, lo half carry-free.
    const int wid  = tid >> 5;
    const int lane = tid & 31;
    #pragma unroll
    for (int r = 0; r < 8; r++) {
        const int b = wid * 8 + r;
        const unsigned int* row = hh + b * HTHREADS;
        unsigned int s = row[lane] + row[lane + 32] + row[lane + 64] + row[lane + 96]
                       + row[lane + 128] + row[lane + 160] + row[lane + 192] + row[lane + 224];
        #pragma unroll
        for (int d = 16; d >= 1; d >>= 1)
            s += __shfl_down_sync(0xFFFFFFFFu, s, d);
        if (lane == 0)
            g_part[blockIdx.x * BINS + b] = (float)((s & 0xFFFFu) + (s >> 16));
    }
}

// MLP with PDL: grid=16 (one image per block), 256 threads.
#define MLP_BLOCKS  16
#define MLP_THREADS 256
#define MLP_SMEM_FLOATS (24576 + 4096 + 192 + 256 + 128 + 128)
#define MLP_SMEM_BYTES  (MLP_SMEM_FLOATS * 4)

__global__ __launch_bounds__(MLP_THREADS, 1)
void mlp_kernel(const float* __restrict__ params, float* __restrict__ out) {
    extern __shared__ float smem[];
    float* s_w1   = smem;                 // [192][128]
    float* s_w2   = s_w1 + 24576;         // [128][32]
    float* s_hist = s_w2 + 4096;          // [192]
    float* s_p1   = s_hist + 192;         // [2][128] layer-1 partials
    float* s_h1   = s_p1 + 256;           // [128]
    float* s_l2   = s_h1 + 128;           // [4][32] layer-2 partials

    const int tid = threadIdx.x;
    const int n   = blockIdx.x;

    // ---- Pre-sync: stage weights (overlaps with hist via PDL) ----
    #pragma unroll
    for (int i = tid; i < 24576 / 4; i += MLP_THREADS)
        reinterpret_cast<float4*>(s_w1)[i] = reinterpret_cast<const float4*>(params + P_W1)[i];
    #pragma unroll
    for (int i = tid; i < 4096 / 4; i += MLP_THREADS)
        reinterpret_cast<float4*>(s_w2)[i] = reinterpret_cast<const float4*>(params + P_W2)[i];

    cudaGridDependencySynchronize();

    if (tid < 192) {
        int c = tid >> 6;
        int b = tid & 63;
        const float* p = g_part + ((n * 3 + c) * BPS) * BINS + b;
        float s = 0.0f;
        #pragma unroll
        for (int k = 0; k < BPS; k++) s += p[k * BINS];
        s_hist[tid] = s;
    }
    __syncthreads();

    // Layer 1: j = tid&127, half = tid>>7 covers c in [half*96, half*96+96)
    {
        const int j    = tid & 127;
        const int half = tid >> 7;
        const int c0   = half * 96;
        float acc = 0.0f;
        #pragma unroll 16
        for (int c = c0; c < c0 + 96; c++)
            acc = fmaf(s_hist[c], s_w1[c * 128 + j], acc);
        s_p1[half * 128 + j] = acc;
    }
    __syncthreads();
    if (tid < 128)
        s_h1[tid] = fmaxf(s_p1[tid] + s_p1[128 + tid] + params[P_B1 + tid], 0.0f);
    __syncthreads();

    if (tid < 128) {
        const int q = tid >> 5;
        const int k = tid & 31;
        float a = 0.0f;
        #pragma unroll
        for (int c = q * 32; c < q * 32 + 32; c++)
            a = fmaf(s_h1[c], s_w2[c * 32 + k], a);
        s_l2[tid] = a;
    }
    __syncthreads();

    if (tid < 32) {
        float a = params[P_B2 + tid] + params[P_G]
                + s_l2[tid] + s_l2[32 + tid] + s_l2[64 + tid] + s_l2[96 + tid];
        out[n * 32 + tid] = 1.0f / (1.0f + expf(-a));
    }
}

extern "C" void kernel_launch(void* const* d_in, const int* in_sizes, int n_in,
                              void* d_out, int out_size) {
    const float* img    = (const float*)d_in[0];
    const float* params = (const float*)d_in[1];
    float* out          = (float*)d_out;

    static bool attr_set = false;
    if (!attr_set) {
        cudaFuncSetAttribute(hist_kernel, cudaFuncAttributeMaxDynamicSharedMemorySize, HSMEM_BYTES);
        cudaFuncSetAttribute(mlp_kernel,  cudaFuncAttributeMaxDynamicSharedMemorySize, MLP_SMEM_BYTES);
        attr_set = true;
    }

    // 4 launches per call so ncu (-s 5 -c 1) lands on hist_kernel (index 5 mod 4 = 1).
    pad_kernel<<<1, 32>>>();
    hist_kernel<<<NBLOCKS, HTHREADS, HSMEM_BYTES>>>(img);

    cudaLaunchConfig_t cfg = {};
    cfg.gridDim  = dim3(MLP_BLOCKS, 1, 1);
    cfg.blockDim = dim3(MLP_THREADS, 1, 1);
    cfg.dynamicSmemBytes = MLP_SMEM_BYTES;
    cudaLaunchAttribute attrs[1];
    attrs[0].id = cudaLaunchAttributeProgrammaticStreamSerialization;
    attrs[0].val.programmaticStreamSerializationAllowed = 1;
    cfg.attrs = attrs;
    cfg.numAttrs = 1;
    cudaLaunchKernelEx(&cfg, mlp_kernel, params, out);

    pad_kernel<<<1, 32>>>();
}